// round 7
// baseline (speedup 1.0000x reference)
#include <cuda_runtime.h>
#include <cstdint>

#define CELLS (1 << 21)        // 128^3 coarse cells, 21-bit key
#define NWORDS (CELLS / 32)    // 65536 bitmask words (256 KB, L2-resident)
#define NBLOCKS 64             // scan blocks: 64 x 256 thr x 4 words
#define MAXN 524288

__device__ __align__(16) unsigned g_mask[NWORDS];   // occupancy bitmask
__device__ __align__(16) unsigned g_wpre[NWORDS];   // exclusive popc prefix per word
__device__ unsigned g_bsum[NBLOCKS];
__device__ unsigned g_numu;
__device__ int g_winner[MAXN * 8];

// ---------------------------------------------------------------------------
__global__ void markK(const int* __restrict__ coords, int n) {
    int i = blockIdx.x * blockDim.x + threadIdx.x;
    if (i >= n) return;
    int cx = coords[3 * i + 0] >> 1;
    int cy = coords[3 * i + 1] >> 1;
    int cz = coords[3 * i + 2] >> 1;
    unsigned key = ((unsigned)cx << 14) | ((unsigned)cy << 7) | (unsigned)cz;
    atomicOr(&g_mask[key >> 5], 1u << (key & 31));
}

// Stage A: per-block popcount sums (64 blocks x 256 thr x 4 words)
__global__ void scanA() {
    int t = threadIdx.x, lane = t & 31, warp = t >> 5;
    const uint4* p = (const uint4*)&g_mask[blockIdx.x * 1024 + t * 4];
    uint4 a = p[0];
    unsigned sum = __popc(a.x) + __popc(a.y) + __popc(a.z) + __popc(a.w);
#pragma unroll
    for (int o = 16; o > 0; o >>= 1) sum += __shfl_down_sync(0xFFFFFFFFu, sum, o);
    __shared__ unsigned ws[8];
    if (lane == 0) ws[warp] = sum;
    __syncthreads();
    if (t == 0) {
        unsigned s = 0;
#pragma unroll
        for (int i = 0; i < 8; i++) s += ws[i];
        g_bsum[blockIdx.x] = s;
    }
}

// Stage B+C fused: per-word exclusive prefix -> g_wpre, plus direct emission
// of the sorted unique coarse coords (mask + rank already in registers).
__global__ void scanC(float* __restrict__ outc) {
    int t = threadIdx.x, lane = t & 31, warp = t >> 5;
    int wbase = blockIdx.x * 1024 + t * 4;
    const uint4* p = (const uint4*)&g_mask[wbase];
    uint4 a = p[0];
    unsigned w0 = a.x, w1 = a.y, w2 = a.z, w3 = a.w;
    unsigned csum = __popc(w0) + __popc(w1) + __popc(w2) + __popc(w3);

    unsigned incl = csum;
#pragma unroll
    for (int o = 1; o < 32; o <<= 1) {
        unsigned y = __shfl_up_sync(0xFFFFFFFFu, incl, o);
        if (lane >= o) incl += y;
    }
    __shared__ unsigned wsum[8];
    __shared__ unsigned sbase;
    if (lane == 31) wsum[warp] = incl;
    __syncthreads();
    if (warp == 0) {
        unsigned v = 0;
        if (lane < (int)blockIdx.x) v += g_bsum[lane];
        if (lane + 32 < (int)blockIdx.x) v += g_bsum[lane + 32];
#pragma unroll
        for (int o = 16; o > 0; o >>= 1) v += __shfl_down_sync(0xFFFFFFFFu, v, o);
        if (lane == 0) sbase = v;
        if (lane < 8) {
            unsigned w = wsum[lane];
#pragma unroll
            for (int o = 1; o < 8; o <<= 1) {
                unsigned y = __shfl_up_sync(0x000000FFu, w, o);
                if (lane >= o) w += y;
            }
            wsum[lane] = w;
        }
    }
    __syncthreads();
    unsigned run = sbase + (warp ? wsum[warp - 1] : 0u) + (incl - csum);

    unsigned words[4] = {w0, w1, w2, w3};
    uint4 pre;
    unsigned* pp = &pre.x;
#pragma unroll
    for (int i = 0; i < 4; i++) {
        pp[i] = run;
        unsigned m = words[i];
        unsigned r = run;
        unsigned kb = (unsigned)(wbase + i) << 5;
        while (m) {
            unsigned b = (unsigned)__ffs(m) - 1u;
            m &= m - 1u;
            unsigned key = kb + b;
            outc[r * 3 + 0] = (float)(key >> 14);
            outc[r * 3 + 1] = (float)((key >> 7) & 127);
            outc[r * 3 + 2] = (float)(key & 127);
            r++;
        }
        run += __popc(words[i]);
    }
    ((uint4*)&g_wpre[wbase])[0] = pre;
    if (blockIdx.x == NBLOCKS - 1 && t == 255) g_numu = run;
}

// Fill only the padding rows (flat float index >= 3*numu) with -1
__global__ void fillTailK(float* __restrict__ outc, int n3) {
    int i = blockIdx.x * blockDim.x + threadIdx.x;
    if (i >= n3 || (unsigned)i < 3u * g_numu) return;
    outc[i] = -1.0f;
}

__device__ __forceinline__ unsigned rank_of(unsigned key) {
    unsigned w = key >> 5, b = key & 31;
    return g_wpre[w] + __popc(g_mask[w] & ((1u << b) - 1u));
}

// Winner resolution: last point index wins per (row, offset) slot
__global__ void winnerK(const int* __restrict__ coords, int n) {
    int i = blockIdx.x * blockDim.x + threadIdx.x;
    if (i >= n) return;
    int x = coords[3 * i + 0];
    int y = coords[3 * i + 1];
    int z = coords[3 * i + 2];
    unsigned key = ((unsigned)(x >> 1) << 14) | ((unsigned)(y >> 1) << 7) | (unsigned)(z >> 1);
    unsigned row = rank_of(key);
    int off = (x & 1) * 4 + (y & 1) * 2 + (z & 1);
    atomicMax(&g_winner[row * 8 + off], i);
}

// Scatter features: 4 threads per point, one float4 each
__global__ void scatterK(const float* __restrict__ feats,
                         const int* __restrict__ coords,
                         float* __restrict__ agg, int n) {
    int j = blockIdx.x * blockDim.x + threadIdx.x;
    int i = j >> 2;
    int q = j & 3;
    if (i >= n) return;
    int x = coords[3 * i + 0];
    int y = coords[3 * i + 1];
    int z = coords[3 * i + 2];
    unsigned key = ((unsigned)(x >> 1) << 14) | ((unsigned)(y >> 1) << 7) | (unsigned)(z >> 1);
    unsigned row = rank_of(key);
    int off = (x & 1) * 4 + (y & 1) * 2 + (z & 1);
    if (g_winner[row * 8 + off] != i) return;  // deterministic last-wins
    float4 v = ((const float4*)feats)[i * 4 + q];
    ((float4*)agg)[(row * 128 + off * 16) / 4 + q] = v;
}

// ---------------------------------------------------------------------------
extern "C" void kernel_launch(void* const* d_in, const int* in_sizes, int n_in,
                              void* d_out, int out_size) {
    const float* feats;
    const int* coords;
    int n;
    if (in_sizes[0] >= in_sizes[1]) {
        feats = (const float*)d_in[0];
        coords = (const int*)d_in[1];
        n = in_sizes[1] / 3;
    } else {
        feats = (const float*)d_in[1];
        coords = (const int*)d_in[0];
        n = in_sizes[0] / 3;
    }

    float* outc = (float*)d_out;            // [N,3] unique coords (as float)
    float* agg = outc + (size_t)n * 3;      // [N,128] aggregated features

    void* p_mask;   cudaGetSymbolAddress(&p_mask, g_mask);
    void* p_winner; cudaGetSymbolAddress(&p_winner, g_winner);

    // One-time side stream + events (created outside capture on the
    // correctness call; reused identically on every call -> deterministic).
    static cudaStream_t s_side = nullptr;
    static cudaEvent_t e_fork = nullptr, e_join = nullptr;
    if (!s_side) {
        cudaStreamCreateWithFlags(&s_side, cudaStreamNonBlocking);
        cudaEventCreateWithFlags(&e_fork, cudaEventDisableTiming);
        cudaEventCreateWithFlags(&e_join, cudaEventDisableTiming);
    }

    // Fork: big 256MB agg zero-fill runs concurrently with the whole
    // small-kernel chain; join before scatterK.
    cudaEventRecord(e_fork, 0);
    cudaStreamWaitEvent(s_side, e_fork, 0);
    cudaMemsetAsync(agg, 0, sizeof(float) * 128 * (size_t)n, s_side);
    cudaEventRecord(e_join, s_side);

    // Main chain (hidden under the big memset)
    cudaMemsetAsync(p_mask, 0, sizeof(unsigned) * NWORDS);
    cudaMemsetAsync(p_winner, 0xFF, sizeof(int) * 8 * (size_t)n);

    int tb = 256;
    markK<<<(n + tb - 1) / tb, tb>>>(coords, n);
    scanA<<<NBLOCKS, tb>>>();
    scanC<<<NBLOCKS, tb>>>(outc);
    fillTailK<<<(n * 3 + tb - 1) / tb, tb>>>(outc, n * 3);
    winnerK<<<(n + tb - 1) / tb, tb>>>(coords, n);

    cudaStreamWaitEvent(0, e_join, 0);
    scatterK<<<(n * 4 + tb - 1) / tb, tb>>>(feats, coords, agg, n);
}

// round 8
// speedup vs baseline: 1.0370x; 1.0370x over previous
#include <cuda_runtime.h>
#include <cstdint>

#define CELLS (1 << 21)        // 128^3 coarse cells, 21-bit key
#define NWORDS (CELLS / 32)    // 65536 bitmask words (256 KB, L2-resident)
#define NBLOCKS 64             // scan blocks: 64 x 256 thr x 4 words
#define MAXN 524288

__device__ __align__(16) unsigned g_mask[NWORDS];   // occupancy bitmask
__device__ __align__(16) unsigned g_wpre[NWORDS];   // exclusive popc prefix per word
__device__ unsigned g_bsum[NBLOCKS];
__device__ unsigned g_numu;
__device__ int g_winner[MAXN * 8];

// ---------------------------------------------------------------------------
// Streaming zero of the 256MB agg region (owned, not driver memset)
__global__ void zeroAggK(float4* __restrict__ agg, int total4) {
    int stride = gridDim.x * blockDim.x;
    float4 z = make_float4(0.f, 0.f, 0.f, 0.f);
    for (int i = blockIdx.x * blockDim.x + threadIdx.x; i < total4; i += stride)
        agg[i] = z;
}

// Pre-fill the whole coords output with -1 (scanC overwrites occupied rows)
__global__ void fillCoordsK(float4* __restrict__ outc, int total4) {
    int i = blockIdx.x * blockDim.x + threadIdx.x;
    if (i < total4) outc[i] = make_float4(-1.f, -1.f, -1.f, -1.f);
}

// ---------------------------------------------------------------------------
__global__ void markK(const int* __restrict__ coords, int n) {
    int i = blockIdx.x * blockDim.x + threadIdx.x;
    if (i >= n) return;
    int cx = coords[3 * i + 0] >> 1;
    int cy = coords[3 * i + 1] >> 1;
    int cz = coords[3 * i + 2] >> 1;
    unsigned key = ((unsigned)cx << 14) | ((unsigned)cy << 7) | (unsigned)cz;
    atomicOr(&g_mask[key >> 5], 1u << (key & 31));
}

// Stage A: per-block popcount sums
__global__ void scanA() {
    int t = threadIdx.x, lane = t & 31, warp = t >> 5;
    const uint4* p = (const uint4*)&g_mask[blockIdx.x * 1024 + t * 4];
    uint4 a = p[0];
    unsigned sum = __popc(a.x) + __popc(a.y) + __popc(a.z) + __popc(a.w);
#pragma unroll
    for (int o = 16; o > 0; o >>= 1) sum += __shfl_down_sync(0xFFFFFFFFu, sum, o);
    __shared__ unsigned ws[8];
    if (lane == 0) ws[warp] = sum;
    __syncthreads();
    if (t == 0) {
        unsigned s = 0;
#pragma unroll
        for (int i = 0; i < 8; i++) s += ws[i];
        g_bsum[blockIdx.x] = s;
    }
}

// Stage B+C fused: per-word exclusive prefix -> g_wpre, plus direct emission
// of the sorted unique coarse coords.
__global__ void scanC(float* __restrict__ outc) {
    int t = threadIdx.x, lane = t & 31, warp = t >> 5;
    int wbase = blockIdx.x * 1024 + t * 4;
    const uint4* p = (const uint4*)&g_mask[wbase];
    uint4 a = p[0];
    unsigned w0 = a.x, w1 = a.y, w2 = a.z, w3 = a.w;
    unsigned csum = __popc(w0) + __popc(w1) + __popc(w2) + __popc(w3);

    unsigned incl = csum;
#pragma unroll
    for (int o = 1; o < 32; o <<= 1) {
        unsigned y = __shfl_up_sync(0xFFFFFFFFu, incl, o);
        if (lane >= o) incl += y;
    }
    __shared__ unsigned wsum[8];
    __shared__ unsigned sbase;
    if (lane == 31) wsum[warp] = incl;
    __syncthreads();
    if (warp == 0) {
        unsigned v = 0;
        if (lane < (int)blockIdx.x) v += g_bsum[lane];
        if (lane + 32 < (int)blockIdx.x) v += g_bsum[lane + 32];
#pragma unroll
        for (int o = 16; o > 0; o >>= 1) v += __shfl_down_sync(0xFFFFFFFFu, v, o);
        if (lane == 0) sbase = v;
        if (lane < 8) {
            unsigned w = wsum[lane];
#pragma unroll
            for (int o = 1; o < 8; o <<= 1) {
                unsigned y = __shfl_up_sync(0x000000FFu, w, o);
                if (lane >= o) w += y;
            }
            wsum[lane] = w;
        }
    }
    __syncthreads();
    unsigned run = sbase + (warp ? wsum[warp - 1] : 0u) + (incl - csum);

    unsigned words[4] = {w0, w1, w2, w3};
    uint4 pre;
    unsigned* pp = &pre.x;
#pragma unroll
    for (int i = 0; i < 4; i++) {
        pp[i] = run;
        unsigned m = words[i];
        unsigned r = run;
        unsigned kb = (unsigned)(wbase + i) << 5;
        while (m) {
            unsigned b = (unsigned)__ffs(m) - 1u;
            m &= m - 1u;
            unsigned key = kb + b;
            outc[r * 3 + 0] = (float)(key >> 14);
            outc[r * 3 + 1] = (float)((key >> 7) & 127);
            outc[r * 3 + 2] = (float)(key & 127);
            r++;
        }
        run += __popc(words[i]);
    }
    ((uint4*)&g_wpre[wbase])[0] = pre;
    if (blockIdx.x == NBLOCKS - 1 && t == 255) g_numu = run;
}

__device__ __forceinline__ unsigned rank_of(unsigned key) {
    unsigned w = key >> 5, b = key & 31;
    return g_wpre[w] + __popc(g_mask[w] & ((1u << b) - 1u));
}

// Winner resolution: last point index wins per (row, offset) slot
__global__ void winnerK(const int* __restrict__ coords, int n) {
    int i = blockIdx.x * blockDim.x + threadIdx.x;
    if (i >= n) return;
    int x = coords[3 * i + 0];
    int y = coords[3 * i + 1];
    int z = coords[3 * i + 2];
    unsigned key = ((unsigned)(x >> 1) << 14) | ((unsigned)(y >> 1) << 7) | (unsigned)(z >> 1);
    unsigned row = rank_of(key);
    int off = (x & 1) * 4 + (y & 1) * 2 + (z & 1);
    atomicMax(&g_winner[row * 8 + off], i);
}

// Scatter features: 4 threads per point, one float4 each
__global__ void scatterK(const float* __restrict__ feats,
                         const int* __restrict__ coords,
                         float* __restrict__ agg, int n) {
    int j = blockIdx.x * blockDim.x + threadIdx.x;
    int i = j >> 2;
    int q = j & 3;
    if (i >= n) return;
    int x = coords[3 * i + 0];
    int y = coords[3 * i + 1];
    int z = coords[3 * i + 2];
    unsigned key = ((unsigned)(x >> 1) << 14) | ((unsigned)(y >> 1) << 7) | (unsigned)(z >> 1);
    unsigned row = rank_of(key);
    int off = (x & 1) * 4 + (y & 1) * 2 + (z & 1);
    if (g_winner[row * 8 + off] != i) return;  // deterministic last-wins
    float4 v = ((const float4*)feats)[i * 4 + q];
    ((float4*)agg)[(row * 128 + off * 16) / 4 + q] = v;
}

// ---------------------------------------------------------------------------
extern "C" void kernel_launch(void* const* d_in, const int* in_sizes, int n_in,
                              void* d_out, int out_size) {
    const float* feats;
    const int* coords;
    int n;
    if (in_sizes[0] >= in_sizes[1]) {
        feats = (const float*)d_in[0];
        coords = (const int*)d_in[1];
        n = in_sizes[1] / 3;
    } else {
        feats = (const float*)d_in[1];
        coords = (const int*)d_in[0];
        n = in_sizes[0] / 3;
    }

    float* outc = (float*)d_out;            // [N,3] unique coords (as float)
    float* agg = outc + (size_t)n * 3;      // [N,128] aggregated features

    void* p_mask;   cudaGetSymbolAddress(&p_mask, g_mask);
    void* p_winner; cudaGetSymbolAddress(&p_winner, g_winner);

    static cudaStream_t s_side = nullptr;
    static cudaEvent_t e_fork = nullptr, e_join = nullptr;
    if (!s_side) {
        cudaStreamCreateWithFlags(&s_side, cudaStreamNonBlocking);
        cudaEventCreateWithFlags(&e_fork, cudaEventDisableTiming);
        cudaEventCreateWithFlags(&e_join, cudaEventDisableTiming);
    }

    int tb = 256;

    // Fork: 256MB agg zero-fill (our own streaming-store kernel) runs
    // concurrently with the small-kernel chain; join before scatterK.
    cudaEventRecord(e_fork, 0);
    cudaStreamWaitEvent(s_side, e_fork, 0);
    int agg4 = n * 32;                       // n*128 floats / 4
    zeroAggK<<<2048, tb, 0, s_side>>>((float4*)agg, agg4);
    cudaEventRecord(e_join, s_side);

    // Main chain (hidden under the big zero-fill)
    cudaMemsetAsync(p_mask, 0, sizeof(unsigned) * NWORDS);
    cudaMemsetAsync(p_winner, 0xFF, sizeof(int) * 8 * (size_t)n);
    fillCoordsK<<<(n * 3 / 4 + tb - 1) / tb, tb>>>((float4*)outc, n * 3 / 4);
    markK<<<(n + tb - 1) / tb, tb>>>(coords, n);
    scanA<<<NBLOCKS, tb>>>();
    scanC<<<NBLOCKS, tb>>>(outc);
    winnerK<<<(n + tb - 1) / tb, tb>>>(coords, n);

    cudaStreamWaitEvent(0, e_join, 0);
    scatterK<<<(n * 4 + tb - 1) / tb, tb>>>(feats, coords, agg, n);
}